// round 1
// baseline (speedup 1.0000x reference)
#include <cuda_runtime.h>
#include <cuda_bf16.h>
#include <cstddef>

// ---------------------------------------------------------------------------
// MMDiT joint attention, fp32 SIMT baseline.
// Shapes: b=2, s_in=2048, s_ctx=256, n=2304, DIM=1536, H=12, D=128.
// ---------------------------------------------------------------------------

#define NH 12
#define HD 128
#define DIM 1536
#define SEQ 2304
#define SCTX 256
#define SIN 2048
#define BATCH 2

// Scratch (device globals; allocation is forbidden).
__device__ float g_qkv_in [ (size_t)BATCH * SIN  * 3 * DIM ];   // 4096 x 4608
__device__ float g_qkv_ctx[ (size_t)BATCH * SCTX * 3 * DIM ];   // 512  x 4608
__device__ float g_q   [ (size_t)BATCH * NH * SEQ * HD ];
__device__ float g_k   [ (size_t)BATCH * NH * SEQ * HD ];
__device__ float g_v   [ (size_t)BATCH * NH * SEQ * HD ];
__device__ float g_attn[ (size_t)BATCH * SEQ * DIM ];

// ---------------------------------------------------------------------------
// SGEMM: C[M,N] = A[M,K] @ B[K,N] + bias[N].  M,N multiples of 128, K of 8.
// 128x128 tile, BK=8, 256 threads, 8x8 microtile.
// ---------------------------------------------------------------------------
__global__ __launch_bounds__(256, 2)
void sgemm_kernel(const float* __restrict__ A, const float* __restrict__ B,
                  const float* __restrict__ bias, float* __restrict__ C,
                  int M, int N, int K)
{
    __shared__ float As[8][128];
    __shared__ float Bs[8][128];

    const int bx = blockIdx.x;   // N tile
    const int by = blockIdx.y;   // M tile
    const int tid = threadIdx.x;
    const int tx = tid & 15;
    const int ty = tid >> 4;

    const int aRow  = tid >> 1;        // 0..127
    const int aCol4 = (tid & 1) * 4;   // 0 or 4
    const int bRow  = tid >> 5;        // 0..7
    const int bCol4 = (tid & 31) * 4;  // 0..124

    const float* Ab = A + (size_t)(by * 128) * K;
    const float* Bb = B + bx * 128;

    float acc[8][8];
#pragma unroll
    for (int i = 0; i < 8; i++)
#pragma unroll
        for (int j = 0; j < 8; j++) acc[i][j] = 0.f;

    for (int k0 = 0; k0 < K; k0 += 8) {
        float4 av = *(const float4*)(Ab + (size_t)aRow * K + k0 + aCol4);
        As[aCol4 + 0][aRow] = av.x;
        As[aCol4 + 1][aRow] = av.y;
        As[aCol4 + 2][aRow] = av.z;
        As[aCol4 + 3][aRow] = av.w;
        float4 bv = *(const float4*)(Bb + (size_t)(k0 + bRow) * N + bCol4);
        *(float4*)&Bs[bRow][bCol4] = bv;
        __syncthreads();

#pragma unroll
        for (int k = 0; k < 8; k++) {
            float a[8], b[8];
            float4 a0 = *(const float4*)&As[k][ty * 4];
            float4 a1 = *(const float4*)&As[k][64 + ty * 4];
            a[0]=a0.x; a[1]=a0.y; a[2]=a0.z; a[3]=a0.w;
            a[4]=a1.x; a[5]=a1.y; a[6]=a1.z; a[7]=a1.w;
            float4 b0 = *(const float4*)&Bs[k][tx * 4];
            float4 b1 = *(const float4*)&Bs[k][64 + tx * 4];
            b[0]=b0.x; b[1]=b0.y; b[2]=b0.z; b[3]=b0.w;
            b[4]=b1.x; b[5]=b1.y; b[6]=b1.z; b[7]=b1.w;
#pragma unroll
            for (int i = 0; i < 8; i++)
#pragma unroll
                for (int j = 0; j < 8; j++)
                    acc[i][j] += a[i] * b[j];
        }
        __syncthreads();
    }

    // Epilogue: bias + store (float4).
#pragma unroll
    for (int i = 0; i < 8; i++) {
        int row = by * 128 + ((i < 4) ? (ty * 4 + i) : (64 + ty * 4 + (i - 4)));
#pragma unroll
        for (int jh = 0; jh < 2; jh++) {
            int col = bx * 128 + ((jh == 0) ? (tx * 4) : (64 + tx * 4));
            float4 o;
            o.x = acc[i][jh * 4 + 0] + bias[col + 0];
            o.y = acc[i][jh * 4 + 1] + bias[col + 1];
            o.z = acc[i][jh * 4 + 2] + bias[col + 2];
            o.w = acc[i][jh * 4 + 3] + bias[col + 3];
            *(float4*)&C[(size_t)row * N + col] = o;
        }
    }
}

// ---------------------------------------------------------------------------
// RMS-norm (over full DIM) + per-channel scale + RoPE + scatter to [b,h,n,d].
// One block per token (b*SEQ blocks, 256 threads).
// ---------------------------------------------------------------------------
__global__ __launch_bounds__(256)
void normrope_kernel(const float* __restrict__ qs_in, const float* __restrict__ ks_in,
                     const float* __restrict__ qs_ctx, const float* __restrict__ ks_ctx)
{
    const int g = blockIdx.x;
    const int b = g / SEQ;
    const int nidx = g % SEQ;

    const float* src;
    const float* qs;
    const float* ks;
    if (nidx < SCTX) {
        src = g_qkv_ctx + ((size_t)b * SCTX + nidx) * (3 * DIM);
        qs = qs_ctx; ks = ks_ctx;
    } else {
        src = g_qkv_in + ((size_t)b * SIN + (nidx - SCTX)) * (3 * DIM);
        qs = qs_in; ks = ks_in;
    }

    __shared__ float sq[DIM];
    __shared__ float sk[DIM];
    __shared__ float red[20];

    const int tid = threadIdx.x;
    float aq = 0.f, ak = 0.f;
    for (int i = tid; i < DIM; i += 256) {
        float qv = src[i];
        float kv = src[DIM + i];
        sq[i] = qv; sk[i] = kv;
        aq += qv * qv; ak += kv * kv;
    }
#pragma unroll
    for (int o = 16; o > 0; o >>= 1) {
        aq += __shfl_xor_sync(0xffffffffu, aq, o);
        ak += __shfl_xor_sync(0xffffffffu, ak, o);
    }
    if ((tid & 31) == 0) { red[tid >> 5] = aq; red[8 + (tid >> 5)] = ak; }
    __syncthreads();
    if (tid == 0) {
        float s = 0.f;
        for (int w = 0; w < 8; w++) s += red[w];
        red[16] = rsqrtf(s / (float)DIM + 1e-6f);
        s = 0.f;
        for (int w = 0; w < 8; w++) s += red[8 + w];
        red[17] = rsqrtf(s / (float)DIM + 1e-6f);
    }
    __syncthreads();
    const float rq = red[16];
    const float rk = red[17];

    // RoPE over pairs (j, j+64) within each head.
    for (int p = tid; p < NH * 64; p += 256) {
        int h = p >> 6;
        int j = p & 63;
        int i1 = h * HD + j;
        int i2 = i1 + 64;
        float q1 = sq[i1] * rq * qs[i1];
        float q2 = sq[i2] * rq * qs[i2];
        float k1 = sk[i1] * rk * ks[i1];
        float k2 = sk[i2] * rk * ks[i2];
        float inv = powf(10000.f, -(float)j / 64.f);
        float ang = (float)nidx * inv;
        float c, s;
        sincosf(ang, &s, &c);
        size_t ob = ((size_t)(b * NH + h) * SEQ + nidx) * HD;
        g_q[ob + j]      = q1 * c - q2 * s;
        g_q[ob + 64 + j] = q2 * c + q1 * s;
        g_k[ob + j]      = k1 * c - k2 * s;
        g_k[ob + 64 + j] = k2 * c + k1 * s;
    }
    // V passthrough.
    for (int i = tid; i < DIM; i += 256) {
        int h = i >> 7;
        int d = i & 127;
        g_v[((size_t)(b * NH + h) * SEQ + nidx) * HD + d] = src[2 * DIM + i];
    }
}

// ---------------------------------------------------------------------------
// Flash attention, fp32. BQ=64, BK=32, D=128, 256 threads (8 warps).
// Warp w owns q-rows w*8..w*8+7. Lane owns k-column = lane and d-cols lane+32j.
// Output written as [b][n][h*128+d].
// ---------------------------------------------------------------------------
#define KPAD 33
#define VPAD 132
#define PPAD 33

__global__ __launch_bounds__(256)
void attn_kernel()
{
    extern __shared__ float sm[];
    float* Qs  = sm;                       // 64*128
    float* Kst = Qs + 64 * 128;            // 128*KPAD (transposed)
    float* Vs  = Kst + 128 * KPAD;         // 32*VPAD
    float* Ps  = Vs + 32 * VPAD;           // 64*PPAD

    const int bh = blockIdx.x;             // 0..23
    const int q0 = blockIdx.y * 64;
    const int b = bh / NH;
    const int h = bh % NH;
    const float* Qb = g_q + (size_t)bh * SEQ * HD;
    const float* Kb = g_k + (size_t)bh * SEQ * HD;
    const float* Vb = g_v + (size_t)bh * SEQ * HD;

    const int tid = threadIdx.x;
    const int warp = tid >> 5;
    const int lane = tid & 31;
    const int qrb = warp * 8;

    // Load Q tile (64x128, float4).
    for (int i = tid; i < 64 * 32; i += 256) {
        int r = i >> 5, c4 = i & 31;
        ((float4*)Qs)[r * 32 + c4] =
            ((const float4*)(Qb + (size_t)(q0 + r) * HD))[c4];
    }

    float m[8], l[8], acc[8][4];
#pragma unroll
    for (int i = 0; i < 8; i++) {
        m[i] = -1e30f; l[i] = 0.f;
#pragma unroll
        for (int j = 0; j < 4; j++) acc[i][j] = 0.f;
    }
    __syncthreads();

    const float scale = 0.08838834764831845f;   // 1/sqrt(128)

    for (int k0 = 0; k0 < SEQ; k0 += 32) {
        // Load K (transposed) + V tiles.
        for (int i = tid; i < 32 * 32; i += 256) {
            int r = i >> 5, c4 = i & 31;
            int d = c4 * 4;
            float4 kv = ((const float4*)(Kb + (size_t)(k0 + r) * HD))[c4];
            Kst[(d + 0) * KPAD + r] = kv.x;
            Kst[(d + 1) * KPAD + r] = kv.y;
            Kst[(d + 2) * KPAD + r] = kv.z;
            Kst[(d + 3) * KPAD + r] = kv.w;
            float4 vv = ((const float4*)(Vb + (size_t)(k0 + r) * HD))[c4];
            *(float4*)&Vs[r * VPAD + d] = vv;
        }
        __syncthreads();

        // Scores: s[i] = Q[qrb+i] . K[lane]
        float s[8];
#pragma unroll
        for (int i = 0; i < 8; i++) s[i] = 0.f;
#pragma unroll 4
        for (int d = 0; d < 128; d += 4) {
            float k0v = Kst[(d + 0) * KPAD + lane];
            float k1v = Kst[(d + 1) * KPAD + lane];
            float k2v = Kst[(d + 2) * KPAD + lane];
            float k3v = Kst[(d + 3) * KPAD + lane];
#pragma unroll
            for (int i = 0; i < 8; i++) {
                float4 qv = *(const float4*)&Qs[(qrb + i) * 128 + d];
                s[i] += qv.x * k0v + qv.y * k1v + qv.z * k2v + qv.w * k3v;
            }
        }

        // Online softmax.
        float corr[8];
#pragma unroll
        for (int i = 0; i < 8; i++) {
            float sv = s[i] * scale;
            float mx = sv;
#pragma unroll
            for (int o = 16; o > 0; o >>= 1)
                mx = fmaxf(mx, __shfl_xor_sync(0xffffffffu, mx, o));
            float mnew = fmaxf(m[i], mx);
            float p = __expf(sv - mnew);
            corr[i] = __expf(m[i] - mnew);
            float ps = p;
#pragma unroll
            for (int o = 16; o > 0; o >>= 1)
                ps += __shfl_xor_sync(0xffffffffu, ps, o);
            l[i] = l[i] * corr[i] + ps;
            m[i] = mnew;
            Ps[(qrb + i) * PPAD + lane] = p;
        }
        __syncwarp();

#pragma unroll
        for (int i = 0; i < 8; i++)
#pragma unroll
            for (int j = 0; j < 4; j++) acc[i][j] *= corr[i];

        // PV: acc[i][j] += sum_k P[i][k] * V[k][lane+32j]
#pragma unroll 4
        for (int kk = 0; kk < 32; kk++) {
            float v0 = Vs[kk * VPAD + lane];
            float v1 = Vs[kk * VPAD + lane + 32];
            float v2 = Vs[kk * VPAD + lane + 64];
            float v3 = Vs[kk * VPAD + lane + 96];
#pragma unroll
            for (int i = 0; i < 8; i++) {
                float p = Ps[(qrb + i) * PPAD + kk];
                acc[i][0] += p * v0;
                acc[i][1] += p * v1;
                acc[i][2] += p * v2;
                acc[i][3] += p * v3;
            }
        }
        __syncthreads();
    }

    // Epilogue -> g_attn[b][n][h*128+d]
#pragma unroll
    for (int i = 0; i < 8; i++) {
        int qr = q0 + qrb + i;
        float inv = 1.f / l[i];
        float* orow = g_attn + ((size_t)b * SEQ + qr) * DIM + h * HD;
        orow[lane]      = acc[i][0] * inv;
        orow[lane + 32] = acc[i][1] * inv;
        orow[lane + 64] = acc[i][2] * inv;
        orow[lane + 96] = acc[i][3] * inv;
    }
}

// ---------------------------------------------------------------------------
// Launch
// ---------------------------------------------------------------------------
extern "C" void kernel_launch(void* const* d_in, const int* in_sizes, int n_in,
                              void* d_out, int out_size)
{
    const float* input     = (const float*)d_in[0];
    const float* context   = (const float*)d_in[1];
    const float* W_qkv_in  = (const float*)d_in[2];
    const float* b_qkv_in  = (const float*)d_in[3];
    const float* W_qkv_ctx = (const float*)d_in[4];
    const float* b_qkv_ctx = (const float*)d_in[5];
    const float* qs_in     = (const float*)d_in[6];
    const float* ks_in     = (const float*)d_in[7];
    const float* qs_ctx    = (const float*)d_in[8];
    const float* ks_ctx    = (const float*)d_in[9];
    const float* W_out_in  = (const float*)d_in[10];
    const float* b_out_in  = (const float*)d_in[11];
    const float* W_out_ctx = (const float*)d_in[12];
    const float* b_out_ctx = (const float*)d_in[13];
    float* out = (float*)d_out;

    float *p_qkv_in, *p_qkv_ctx, *p_attn;
    cudaGetSymbolAddress((void**)&p_qkv_in, g_qkv_in);
    cudaGetSymbolAddress((void**)&p_qkv_ctx, g_qkv_ctx);
    cudaGetSymbolAddress((void**)&p_attn, g_attn);

    // 1) QKV projections
    {
        dim3 grid(3 * DIM / 128, (BATCH * SIN) / 128);     // 36 x 32
        sgemm_kernel<<<grid, 256>>>(input, W_qkv_in, b_qkv_in, p_qkv_in,
                                    BATCH * SIN, 3 * DIM, DIM);
    }
    {
        dim3 grid(3 * DIM / 128, (BATCH * SCTX) / 128);    // 36 x 4
        sgemm_kernel<<<grid, 256>>>(context, W_qkv_ctx, b_qkv_ctx, p_qkv_ctx,
                                    BATCH * SCTX, 3 * DIM, DIM);
    }

    // 2) RMS norm + RoPE + scatter
    normrope_kernel<<<BATCH * SEQ, 256>>>(qs_in, ks_in, qs_ctx, ks_ctx);

    // 3) Attention
    {
        size_t smem = (size_t)(64 * 128 + 128 * KPAD + 32 * VPAD + 64 * PPAD) * 4;
        cudaFuncSetAttribute(attn_kernel,
                             cudaFuncAttributeMaxDynamicSharedMemorySize,
                             (int)smem);
        dim3 grid(BATCH * NH, SEQ / 64);                   // 24 x 36
        attn_kernel<<<grid, 256, smem>>>();
    }

    // 4) Output projections (input part first, then context part)
    for (int b = 0; b < BATCH; b++) {
        dim3 grid(DIM / 128, SIN / 128);                   // 12 x 16
        sgemm_kernel<<<grid, 256>>>(
            p_attn + ((size_t)b * SEQ + SCTX) * DIM,
            W_out_in, b_out_in,
            out + (size_t)b * SIN * DIM,
            SIN, DIM, DIM);
    }
    for (int b = 0; b < BATCH; b++) {
        dim3 grid(DIM / 128, SCTX / 128);                  // 12 x 2
        sgemm_kernel<<<grid, 256>>>(
            p_attn + (size_t)b * SEQ * DIM,
            W_out_ctx, b_out_ctx,
            out + (size_t)BATCH * SIN * DIM + (size_t)b * SCTX * DIM,
            SCTX, DIM, DIM);
    }
}

// round 10
// speedup vs baseline: 5.2558x; 5.2558x over previous
#include <cuda_runtime.h>
#include <cuda_fp16.h>
#include <cuda_bf16.h>
#include <cstdint>
#include <cstddef>

// ---------------------------------------------------------------------------
// MMDiT joint attention. Full HMMA (mma.sync fp16): linear layers + attention.
// Shapes: b=2, s_in=2048, s_ctx=256, n=2304, DIM=1536, H=12, D=128.
// ---------------------------------------------------------------------------

#define NH 12
#define HD 128
#define DIM 1536
#define SEQ 2304
#define SCTX 256
#define SIN 2048
#define BATCH 2

// fp32 scratch
__device__ float g_qkv_in [ (size_t)BATCH * SIN  * 3 * DIM ];
__device__ float g_qkv_ctx[ (size_t)BATCH * SCTX * 3 * DIM ];
__device__ float g_q   [ (size_t)BATCH * NH * SEQ * HD ];
__device__ float g_k   [ (size_t)BATCH * NH * SEQ * HD ];
__device__ float g_v   [ (size_t)BATCH * NH * SEQ * HD ];

// fp16 scratch (GEMM operands, K-major)
__device__ __half g_in_h   [ (size_t)BATCH * SIN  * DIM ];
__device__ __half g_ctx_h  [ (size_t)BATCH * SCTX * DIM ];
__device__ __half g_attn_h [ (size_t)BATCH * SEQ  * DIM ];
__device__ __half g_wqkv_in_h [ (size_t)3 * DIM * DIM ];   // [N=4608][K=1536]
__device__ __half g_wqkv_ctx_h[ (size_t)3 * DIM * DIM ];
__device__ __half g_wout_in_h [ (size_t)DIM * DIM ];
__device__ __half g_wout_ctx_h[ (size_t)DIM * DIM ];

// ---------------------------------------------------------------------------
// helpers
// ---------------------------------------------------------------------------
__device__ __forceinline__ uint32_t smem_u32(const void* p) {
    uint32_t a;
    asm("{ .reg .u64 t; cvta.to.shared.u64 t, %1; cvt.u32.u64 %0, t; }"
        : "=r"(a) : "l"(p));
    return a;
}

#define LDMATRIX_X4(r0, r1, r2, r3, addr) \
    asm volatile("ldmatrix.sync.aligned.m8n8.x4.shared.b16 {%0,%1,%2,%3}, [%4];" \
                 : "=r"(r0), "=r"(r1), "=r"(r2), "=r"(r3) : "r"(addr))

// Non-trans: for operands stored [n][k] row-major (n=lane>>2, k=2(lane&3)+{0,1}).
#define LDMATRIX_X2(r0, r1, addr) \
    asm volatile("ldmatrix.sync.aligned.m8n8.x2.shared.b16 {%0,%1}, [%2];" \
                 : "=r"(r0), "=r"(r1) : "r"(addr))

// Trans: for operands stored [k][n] row-major (V in PV GEMM).
#define LDMATRIX_X2T(r0, r1, addr) \
    asm volatile("ldmatrix.sync.aligned.m8n8.x2.trans.shared.b16 {%0,%1}, [%2];" \
                 : "=r"(r0), "=r"(r1) : "r"(addr))

#define MMA16816(d, a, b) \
    asm volatile("mma.sync.aligned.m16n8k16.row.col.f32.f16.f16.f32 " \
                 "{%0,%1,%2,%3}, {%4,%5,%6,%7}, {%8,%9}, {%0,%1,%2,%3};" \
                 : "+f"((d)[0]), "+f"((d)[1]), "+f"((d)[2]), "+f"((d)[3]) \
                 : "r"((a)[0]), "r"((a)[1]), "r"((a)[2]), "r"((a)[3]), \
                   "r"((b)[0]), "r"((b)[1]))

// ---------------------------------------------------------------------------
// fp32 -> fp16 convert (n multiple of 4)
// ---------------------------------------------------------------------------
__global__ void f2h_kernel(const float* __restrict__ in, __half* __restrict__ out, int n4)
{
    int i = blockIdx.x * 256 + threadIdx.x;
    if (i < n4) {
        float4 v = ((const float4*)in)[i];
        ((__half2*)out)[i * 2]     = __floats2half2_rn(v.x, v.y);
        ((__half2*)out)[i * 2 + 1] = __floats2half2_rn(v.z, v.w);
    }
}

// ---------------------------------------------------------------------------
// Transpose fp32 [R,C] -> fp16 [C,R]
// ---------------------------------------------------------------------------
__global__ __launch_bounds__(256)
void transpose_h_kernel(const float* __restrict__ in, __half* __restrict__ out,
                        int R, int C)
{
    __shared__ float t[32][33];
    int c0 = blockIdx.x * 32, r0 = blockIdx.y * 32;
    int x = threadIdx.x, y = threadIdx.y;
#pragma unroll
    for (int i = 0; i < 32; i += 8)
        t[y + i][x] = in[(size_t)(r0 + y + i) * C + c0 + x];
    __syncthreads();
#pragma unroll
    for (int i = 0; i < 32; i += 8)
        out[(size_t)(c0 + y + i) * R + r0 + x] = __float2half(t[x][y + i]);
}

// ---------------------------------------------------------------------------
// HMMA fp16 GEMM: C[M,N] = A[M,K] @ B[N,K]^T + bias[N]
// 128x128 tile, BK=32, 256 threads (8 warps, 2x4), warp tile 64x32.
// ---------------------------------------------------------------------------
#define SKEW 8
#define LDH (32 + SKEW)

__global__ __launch_bounds__(256)
void gemm_hmma_kernel(const __half* __restrict__ A, const __half* __restrict__ B,
                      const float* __restrict__ bias, float* __restrict__ C,
                      int M, int N, int K)
{
    __shared__ __half sA[128][LDH];
    __shared__ __half sB[128][LDH];

    const int tid = threadIdx.x;
    const int wid = tid >> 5, lane = tid & 31;
    const int wm = (wid >> 2) * 64;
    const int wn = (wid & 3) * 32;
    const int m0 = blockIdx.y * 128, n0 = blockIdx.x * 128;

    const int lr = tid >> 2;
    const int lc = (tid & 3) * 8;

    const __half* Ag = A + (size_t)m0 * K;
    const __half* Bg = B + (size_t)n0 * K;

    float acc[4][4][4];
#pragma unroll
    for (int i = 0; i < 4; i++)
#pragma unroll
        for (int j = 0; j < 4; j++)
#pragma unroll
            for (int r = 0; r < 4; r++) acc[i][j][r] = 0.f;

    const uint32_t sA_u = smem_u32(&sA[0][0]);
    const uint32_t sB_u = smem_u32(&sB[0][0]);

    const int a_row = wm + (lane & 15);
    const int a_col = (lane >> 4) * 8;
    const int b_row = wn + (lane & 7);
    const int b_col = ((lane >> 3) & 1) * 8;

    const int nstage = K >> 5;

    *(uint4*)&sA[lr][lc]      = *(const uint4*)(Ag + (size_t)lr * K + lc);
    *(uint4*)&sA[lr + 64][lc] = *(const uint4*)(Ag + (size_t)(lr + 64) * K + lc);
    *(uint4*)&sB[lr][lc]      = *(const uint4*)(Bg + (size_t)lr * K + lc);
    *(uint4*)&sB[lr + 64][lc] = *(const uint4*)(Bg + (size_t)(lr + 64) * K + lc);
    __syncthreads();

    uint4 pa0, pa1, pb0, pb1;
    for (int st = 0; st < nstage; st++) {
        const bool pf = (st + 1) < nstage;
        if (pf) {
            const int kn = (st + 1) << 5;
            pa0 = *(const uint4*)(Ag + (size_t)lr * K + kn + lc);
            pa1 = *(const uint4*)(Ag + (size_t)(lr + 64) * K + kn + lc);
            pb0 = *(const uint4*)(Bg + (size_t)lr * K + kn + lc);
            pb1 = *(const uint4*)(Bg + (size_t)(lr + 64) * K + kn + lc);
        }

#pragma unroll
        for (int ks = 0; ks < 2; ks++) {
            uint32_t af[4][4];
            uint32_t bf[4][2];
#pragma unroll
            for (int mt = 0; mt < 4; mt++) {
                uint32_t addr = sA_u +
                    (uint32_t)(((a_row + mt * 16) * LDH + ks * 16 + a_col) * 2);
                LDMATRIX_X4(af[mt][0], af[mt][1], af[mt][2], af[mt][3], addr);
            }
#pragma unroll
            for (int nt = 0; nt < 4; nt++) {
                uint32_t addr = sB_u +
                    (uint32_t)(((b_row + nt * 8) * LDH + ks * 16 + b_col) * 2);
                LDMATRIX_X2(bf[nt][0], bf[nt][1], addr);
            }
#pragma unroll
            for (int mt = 0; mt < 4; mt++)
#pragma unroll
                for (int nt = 0; nt < 4; nt++)
                    MMA16816(acc[mt][nt], af[mt], bf[nt]);
        }
        __syncthreads();
        if (pf) {
            *(uint4*)&sA[lr][lc] = pa0;
            *(uint4*)&sA[lr + 64][lc] = pa1;
            *(uint4*)&sB[lr][lc] = pb0;
            *(uint4*)&sB[lr + 64][lc] = pb1;
            __syncthreads();
        }
    }

    const int er = lane >> 2;
    const int ec = (lane & 3) * 2;
#pragma unroll
    for (int mt = 0; mt < 4; mt++) {
#pragma unroll
        for (int nt = 0; nt < 4; nt++) {
            int row = m0 + wm + mt * 16 + er;
            int col = n0 + wn + nt * 8 + ec;
            float2 bv = *(const float2*)&bias[col];
            float2 o;
            o.x = acc[mt][nt][0] + bv.x;
            o.y = acc[mt][nt][1] + bv.y;
            *(float2*)&C[(size_t)row * N + col] = o;
            o.x = acc[mt][nt][2] + bv.x;
            o.y = acc[mt][nt][3] + bv.y;
            *(float2*)&C[(size_t)(row + 8) * N + col] = o;
        }
    }
}

// ---------------------------------------------------------------------------
// RMS-norm + scale + RoPE + scatter
// ---------------------------------------------------------------------------
__global__ __launch_bounds__(256)
void normrope_kernel(const float* __restrict__ qs_in, const float* __restrict__ ks_in,
                     const float* __restrict__ qs_ctx, const float* __restrict__ ks_ctx)
{
    const int g = blockIdx.x;
    const int b = g / SEQ;
    const int nidx = g % SEQ;

    const float* src;
    const float* qs;
    const float* ks;
    if (nidx < SCTX) {
        src = g_qkv_ctx + ((size_t)b * SCTX + nidx) * (3 * DIM);
        qs = qs_ctx; ks = ks_ctx;
    } else {
        src = g_qkv_in + ((size_t)b * SIN + (nidx - SCTX)) * (3 * DIM);
        qs = qs_in; ks = ks_in;
    }

    __shared__ float sq[DIM];
    __shared__ float sk[DIM];
    __shared__ float red[20];

    const int tid = threadIdx.x;
    float aq = 0.f, ak = 0.f;
    for (int i = tid; i < DIM; i += 256) {
        float qv = src[i];
        float kv = src[DIM + i];
        sq[i] = qv; sk[i] = kv;
        aq += qv * qv; ak += kv * kv;
    }
#pragma unroll
    for (int o = 16; o > 0; o >>= 1) {
        aq += __shfl_xor_sync(0xffffffffu, aq, o);
        ak += __shfl_xor_sync(0xffffffffu, ak, o);
    }
    if ((tid & 31) == 0) { red[tid >> 5] = aq; red[8 + (tid >> 5)] = ak; }
    __syncthreads();
    if (tid == 0) {
        float s = 0.f;
        for (int w = 0; w < 8; w++) s += red[w];
        red[16] = rsqrtf(s / (float)DIM + 1e-6f);
        s = 0.f;
        for (int w = 0; w < 8; w++) s += red[8 + w];
        red[17] = rsqrtf(s / (float)DIM + 1e-6f);
    }
    __syncthreads();
    const float rq = red[16];
    const float rk = red[17];

    for (int p = tid; p < NH * 64; p += 256) {
        int h = p >> 6;
        int j = p & 63;
        int i1 = h * HD + j;
        int i2 = i1 + 64;
        float q1 = sq[i1] * rq * qs[i1];
        float q2 = sq[i2] * rq * qs[i2];
        float k1 = sk[i1] * rk * ks[i1];
        float k2 = sk[i2] * rk * ks[i2];
        float inv = powf(10000.f, -(float)j / 64.f);
        float ang = (float)nidx * inv;
        float c, s;
        sincosf(ang, &s, &c);
        size_t ob = ((size_t)(b * NH + h) * SEQ + nidx) * HD;
        g_q[ob + j]      = q1 * c - q2 * s;
        g_q[ob + 64 + j] = q2 * c + q1 * s;
        g_k[ob + j]      = k1 * c - k2 * s;
        g_k[ob + 64 + j] = k2 * c + k1 * s;
    }
    for (int i = tid; i < DIM; i += 256) {
        int h = i >> 7;
        int d = i & 127;
        g_v[((size_t)(b * NH + h) * SEQ + nidx) * HD + d] = src[2 * DIM + i];
    }
}

// ---------------------------------------------------------------------------
// Flash attention, HMMA fp16. BQ=64, BK=64, D=128, 128 threads (4 warps).
// Warp w owns q-rows wm=w*16..+15 (one m16 tile).
// Output written as fp16 to g_attn_h[b][n][h*128+d].
// ---------------------------------------------------------------------------
#define APAD 136   // 128 + 8 halves per row

__global__ __launch_bounds__(128)
void attn_hmma_kernel()
{
    extern __shared__ __half smh[];
    __half* Qs = smh;                  // 64 x APAD
    __half* Ks = Qs + 64 * APAD;       // 64 x APAD
    __half* Vs = Ks + 64 * APAD;       // 64 x APAD

    const int bh = blockIdx.x;
    const int q0 = blockIdx.y * 64;
    const int b = bh / NH;
    const int h = bh % NH;
    const float* Qb = g_q + (size_t)bh * SEQ * HD;
    const float* Kb = g_k + (size_t)bh * SEQ * HD;
    const float* Vb = g_v + (size_t)bh * SEQ * HD;

    const int tid = threadIdx.x;
    const int wid = tid >> 5, lane = tid & 31;
    const int wm = wid * 16;           // warp's q-row base within tile
    const int r  = lane >> 2;          // fragment row (r and r+8)
    const int qc = (lane & 3) * 2;     // fragment col pair base

    const uint32_t Qs_u = smem_u32(Qs);
    const uint32_t Ks_u = smem_u32(Ks);
    const uint32_t Vs_u = smem_u32(Vs);

    // Load Q tile fp32 -> fp16 smem
    for (int i = tid; i < 64 * 32; i += 128) {
        int row = i >> 5, c4 = i & 31;
        float4 v = ((const float4*)(Qb + (size_t)(q0 + row) * HD))[c4];
        __half* dst = Qs + row * APAD + c4 * 4;
        ((__half2*)dst)[0] = __floats2half2_rn(v.x, v.y);
        ((__half2*)dst)[1] = __floats2half2_rn(v.z, v.w);
    }

    float oacc[16][4];
#pragma unroll
    for (int dt = 0; dt < 16; dt++)
#pragma unroll
        for (int j = 0; j < 4; j++) oacc[dt][j] = 0.f;
    float mrow0 = -1e30f, mrow1 = -1e30f;
    float lrow0 = 0.f,    lrow1 = 0.f;

    const float scale = 0.08838834764831845f;   // 1/sqrt(128)

    for (int k0 = 0; k0 < SEQ; k0 += 64) {
        // Load K, V tiles fp32 -> fp16 smem
        for (int i = tid; i < 64 * 32; i += 128) {
            int row = i >> 5, c4 = i & 31;
            float4 kv = ((const float4*)(Kb + (size_t)(k0 + row) * HD))[c4];
            __half* kd = Ks + row * APAD + c4 * 4;
            ((__half2*)kd)[0] = __floats2half2_rn(kv.x, kv.y);
            ((__half2*)kd)[1] = __floats2half2_rn(kv.z, kv.w);
            float4 vv = ((const float4*)(Vb + (size_t)(k0 + row) * HD))[c4];
            __half* vd = Vs + row * APAD + c4 * 4;
            ((__half2*)vd)[0] = __floats2half2_rn(vv.x, vv.y);
            ((__half2*)vd)[1] = __floats2half2_rn(vv.z, vv.w);
        }
        __syncthreads();

        // Scores S[16][64] = Q_tile . K_tile^T  (8 kd-chunks of 16 over D=128)
        float sacc[8][4];
#pragma unroll
        for (int nt = 0; nt < 8; nt++)
#pragma unroll
            for (int j = 0; j < 4; j++) sacc[nt][j] = 0.f;

#pragma unroll
        for (int kd = 0; kd < 8; kd++) {
            uint32_t af[4];
            uint32_t a_addr = Qs_u +
                (uint32_t)(((wm + (lane & 15)) * APAD + kd * 16 + (lane >> 4) * 8) * 2);
            LDMATRIX_X4(af[0], af[1], af[2], af[3], a_addr);
#pragma unroll
            for (int nt = 0; nt < 8; nt++) {
                uint32_t bf[2];
                uint32_t b_addr = Ks_u +
                    (uint32_t)(((nt * 8 + (lane & 7)) * APAD + kd * 16 + ((lane >> 3) & 1) * 8) * 2);
                LDMATRIX_X2(bf[0], bf[1], b_addr);
                MMA16816(sacc[nt], af, bf);
            }
        }

        // Online softmax on fragments (rows wm+r via c0/c1, wm+r+8 via c2/c3).
        float mx0 = -1e30f, mx1 = -1e30f;
#pragma unroll
        for (int nt = 0; nt < 8; nt++) {
            sacc[nt][0] *= scale; sacc[nt][1] *= scale;
            sacc[nt][2] *= scale; sacc[nt][3] *= scale;
            mx0 = fmaxf(mx0, fmaxf(sacc[nt][0], sacc[nt][1]));
            mx1 = fmaxf(mx1, fmaxf(sacc[nt][2], sacc[nt][3]));
        }
        mx0 = fmaxf(mx0, __shfl_xor_sync(0xffffffffu, mx0, 1));
        mx0 = fmaxf(mx0, __shfl_xor_sync(0xffffffffu, mx0, 2));
        mx1 = fmaxf(mx1, __shfl_xor_sync(0xffffffffu, mx1, 1));
        mx1 = fmaxf(mx1, __shfl_xor_sync(0xffffffffu, mx1, 2));

        float mn0 = fmaxf(mrow0, mx0);
        float mn1 = fmaxf(mrow1, mx1);
        float corr0 = __expf(mrow0 - mn0);
        float corr1 = __expf(mrow1 - mn1);

        float s0 = 0.f, s1 = 0.f;
#pragma unroll
        for (int nt = 0; nt < 8; nt++) {
            sacc[nt][0] = __expf(sacc[nt][0] - mn0);
            sacc[nt][1] = __expf(sacc[nt][1] - mn0);
            sacc[nt][2] = __expf(sacc[nt][2] - mn1);
            sacc[nt][3] = __expf(sacc[nt][3] - mn1);
            s0 += sacc[nt][0] + sacc[nt][1];
            s1 += sacc[nt][2] + sacc[nt][3];
        }
        s0 += __shfl_xor_sync(0xffffffffu, s0, 1);
        s0 += __shfl_xor_sync(0xffffffffu, s0, 2);
        s1 += __shfl_xor_sync(0xffffffffu, s1, 1);
        s1 += __shfl_xor_sync(0xffffffffu, s1, 2);

        lrow0 = lrow0 * corr0 + s0;  mrow0 = mn0;
        lrow1 = lrow1 * corr1 + s1;  mrow1 = mn1;

#pragma unroll
        for (int dt = 0; dt < 16; dt++) {
            oacc[dt][0] *= corr0; oacc[dt][1] *= corr0;
            oacc[dt][2] *= corr1; oacc[dt][3] *= corr1;
        }

        // P -> fp16 A-fragments (C-fragment lane layout == A-fragment layout)
        uint32_t pf[4][4];
#pragma unroll
        for (int kt = 0; kt < 4; kt++) {
            __half2 h0 = __floats2half2_rn(sacc[2 * kt][0],     sacc[2 * kt][1]);
            __half2 h1 = __floats2half2_rn(sacc[2 * kt][2],     sacc[2 * kt][3]);
            __half2 h2 = __floats2half2_rn(sacc[2 * kt + 1][0], sacc[2 * kt + 1][1]);
            __half2 h3 = __floats2half2_rn(sacc[2 * kt + 1][2], sacc[2 * kt + 1][3]);
            pf[kt][0] = *(uint32_t*)&h0;
            pf[kt][1] = *(uint32_t*)&h1;
            pf[kt][2] = *(uint32_t*)&h2;
            pf[kt][3] = *(uint32_t*)&h3;
        }

        // O += P . V   (V via trans ldmatrix from [s][d] storage)
        const int v_row = (lane & 7) + 8 * ((lane >> 3) & 1);
#pragma unroll
        for (int dt = 0; dt < 16; dt++) {
#pragma unroll
            for (int kt = 0; kt < 4; kt++) {
                uint32_t vf[2];
                uint32_t v_addr = Vs_u +
                    (uint32_t)(((kt * 16 + v_row) * APAD + dt * 8) * 2);
                LDMATRIX_X2T(vf[0], vf[1], v_addr);
                MMA16816(oacc[dt], pf[kt], vf);
            }
        }
        __syncthreads();
    }

    // Epilogue -> g_attn_h[b][q][h*128+d], fp16
    float inv0 = 1.f / lrow0;
    float inv1 = 1.f / lrow1;
    int qrow0 = q0 + wm + r;
    int qrow1 = qrow0 + 8;
    __half* o0 = g_attn_h + ((size_t)b * SEQ + qrow0) * DIM + h * HD;
    __half* o1 = g_attn_h + ((size_t)b * SEQ + qrow1) * DIM + h * HD;
#pragma unroll
    for (int dt = 0; dt < 16; dt++) {
        __half2 w0 = __floats2half2_rn(oacc[dt][0] * inv0, oacc[dt][1] * inv0);
        __half2 w1 = __floats2half2_rn(oacc[dt][2] * inv1, oacc[dt][3] * inv1);
        *(__half2*)(o0 + dt * 8 + qc) = w0;
        *(__half2*)(o1 + dt * 8 + qc) = w1;
    }
}

// ---------------------------------------------------------------------------
// Launch
// ---------------------------------------------------------------------------
extern "C" void kernel_launch(void* const* d_in, const int* in_sizes, int n_in,
                              void* d_out, int out_size)
{
    const float* input     = (const float*)d_in[0];
    const float* context   = (const float*)d_in[1];
    const float* W_qkv_in  = (const float*)d_in[2];
    const float* b_qkv_in  = (const float*)d_in[3];
    const float* W_qkv_ctx = (const float*)d_in[4];
    const float* b_qkv_ctx = (const float*)d_in[5];
    const float* qs_in     = (const float*)d_in[6];
    const float* ks_in     = (const float*)d_in[7];
    const float* qs_ctx    = (const float*)d_in[8];
    const float* ks_ctx    = (const float*)d_in[9];
    const float* W_out_in  = (const float*)d_in[10];
    const float* b_out_in  = (const float*)d_in[11];
    const float* W_out_ctx = (const float*)d_in[12];
    const float* b_out_ctx = (const float*)d_in[13];
    float* out = (float*)d_out;

    float *p_qkv_in, *p_qkv_ctx;
    __half *p_in_h, *p_ctx_h, *p_attn_h;
    __half *p_wqi, *p_wqc, *p_woi, *p_woc;
    cudaGetSymbolAddress((void**)&p_qkv_in, g_qkv_in);
    cudaGetSymbolAddress((void**)&p_qkv_ctx, g_qkv_ctx);
    cudaGetSymbolAddress((void**)&p_in_h, g_in_h);
    cudaGetSymbolAddress((void**)&p_ctx_h, g_ctx_h);
    cudaGetSymbolAddress((void**)&p_attn_h, g_attn_h);
    cudaGetSymbolAddress((void**)&p_wqi, g_wqkv_in_h);
    cudaGetSymbolAddress((void**)&p_wqc, g_wqkv_ctx_h);
    cudaGetSymbolAddress((void**)&p_woi, g_wout_in_h);
    cudaGetSymbolAddress((void**)&p_woc, g_wout_ctx_h);

    // 0) Convert activations + transpose weights to fp16 K-major
    {
        int n4 = (BATCH * SIN * DIM) / 4;
        f2h_kernel<<<(n4 + 255) / 256, 256>>>(input, p_in_h, n4);
        n4 = (BATCH * SCTX * DIM) / 4;
        f2h_kernel<<<(n4 + 255) / 256, 256>>>(context, p_ctx_h, n4);
    }
    {
        dim3 blk(32, 8);
        dim3 g1(3 * DIM / 32, DIM / 32);
        transpose_h_kernel<<<g1, blk>>>(W_qkv_in, p_wqi, DIM, 3 * DIM);
        transpose_h_kernel<<<g1, blk>>>(W_qkv_ctx, p_wqc, DIM, 3 * DIM);
        dim3 g2(DIM / 32, DIM / 32);
        transpose_h_kernel<<<g2, blk>>>(W_out_in, p_woi, DIM, DIM);
        transpose_h_kernel<<<g2, blk>>>(W_out_ctx, p_woc, DIM, DIM);
    }

    // 1) QKV projections (HMMA fp16)
    {
        dim3 grid(3 * DIM / 128, (BATCH * SIN) / 128);     // 36 x 32
        gemm_hmma_kernel<<<grid, 256>>>(p_in_h, p_wqi, b_qkv_in, p_qkv_in,
                                        BATCH * SIN, 3 * DIM, DIM);
    }
    {
        dim3 grid(3 * DIM / 128, (BATCH * SCTX) / 128);    // 36 x 4
        gemm_hmma_kernel<<<grid, 256>>>(p_ctx_h, p_wqc, b_qkv_ctx, p_qkv_ctx,
                                        BATCH * SCTX, 3 * DIM, DIM);
    }

    // 2) RMS norm + RoPE + scatter
    normrope_kernel<<<BATCH * SEQ, 256>>>(qs_in, ks_in, qs_ctx, ks_ctx);

    // 3) Attention (HMMA fp16, fp32 softmax) -> writes g_attn_h directly
    {
        size_t smem = (size_t)3 * 64 * APAD * sizeof(__half);   // 52224 B
        cudaFuncSetAttribute(attn_hmma_kernel,
                             cudaFuncAttributeMaxDynamicSharedMemorySize,
                             (int)smem);
        dim3 grid(BATCH * NH, SEQ / 64);                   // 24 x 36
        attn_hmma_kernel<<<grid, 128, smem>>>();
    }

    // 4) Output projections (HMMA fp16)
    for (int b = 0; b < BATCH; b++) {
        dim3 grid(DIM / 128, SIN / 128);                   // 12 x 16
        gemm_hmma_kernel<<<grid, 256>>>(
            p_attn_h + ((size_t)b * SEQ + SCTX) * DIM,
            p_woi, b_out_in,
            out + (size_t)b * SIN * DIM,
            SIN, DIM, DIM);
    }
    for (int b = 0; b < BATCH; b++) {
        dim3 grid(DIM / 128, SCTX / 128);                  // 12 x 2
        gemm_hmma_kernel<<<grid, 256>>>(
            p_attn_h + (size_t)b * SEQ * DIM,
            p_woc, b_out_ctx,
            out + (size_t)BATCH * SIN * DIM + (size_t)b * SCTX * DIM,
            SCTX, DIM, DIM);
    }
}

// round 16
// speedup vs baseline: 5.9645x; 1.1348x over previous
#include <cuda_runtime.h>
#include <cuda_fp16.h>
#include <cuda_bf16.h>
#include <cstdint>
#include <cstddef>

// ---------------------------------------------------------------------------
// MMDiT joint attention. Full HMMA (mma.sync fp16): linear layers + attention.
// Q/K/V stored fp16 (same rounding point as before — precision-neutral).
// Shapes: b=2, s_in=2048, s_ctx=256, n=2304, DIM=1536, H=12, D=128.
// ---------------------------------------------------------------------------

#define NH 12
#define HD 128
#define DIM 1536
#define SEQ 2304
#define SCTX 256
#define SIN 2048
#define BATCH 2

// fp32 scratch
__device__ float g_qkv_in [ (size_t)BATCH * SIN  * 3 * DIM ];
__device__ float g_qkv_ctx[ (size_t)BATCH * SCTX * 3 * DIM ];

// fp16 scratch
__device__ __half g_q_h  [ (size_t)BATCH * NH * SEQ * HD ];
__device__ __half g_k_h  [ (size_t)BATCH * NH * SEQ * HD ];
__device__ __half g_v_h  [ (size_t)BATCH * NH * SEQ * HD ];
__device__ __half g_in_h   [ (size_t)BATCH * SIN  * DIM ];
__device__ __half g_ctx_h  [ (size_t)BATCH * SCTX * DIM ];
__device__ __half g_attn_h [ (size_t)BATCH * SEQ  * DIM ];
__device__ __half g_wqkv_in_h [ (size_t)3 * DIM * DIM ];   // [N=4608][K=1536]
__device__ __half g_wqkv_ctx_h[ (size_t)3 * DIM * DIM ];
__device__ __half g_wout_in_h [ (size_t)DIM * DIM ];
__device__ __half g_wout_ctx_h[ (size_t)DIM * DIM ];

// ---------------------------------------------------------------------------
// helpers
// ---------------------------------------------------------------------------
__device__ __forceinline__ uint32_t smem_u32(const void* p) {
    uint32_t a;
    asm("{ .reg .u64 t; cvta.to.shared.u64 t, %1; cvt.u32.u64 %0, t; }"
        : "=r"(a) : "l"(p));
    return a;
}

#define LDMATRIX_X4(r0, r1, r2, r3, addr) \
    asm volatile("ldmatrix.sync.aligned.m8n8.x4.shared.b16 {%0,%1,%2,%3}, [%4];" \
                 : "=r"(r0), "=r"(r1), "=r"(r2), "=r"(r3) : "r"(addr))

#define LDMATRIX_X2(r0, r1, addr) \
    asm volatile("ldmatrix.sync.aligned.m8n8.x2.shared.b16 {%0,%1}, [%2];" \
                 : "=r"(r0), "=r"(r1) : "r"(addr))

#define LDMATRIX_X2T(r0, r1, addr) \
    asm volatile("ldmatrix.sync.aligned.m8n8.x2.trans.shared.b16 {%0,%1}, [%2];" \
                 : "=r"(r0), "=r"(r1) : "r"(addr))

#define MMA16816(d, a, b) \
    asm volatile("mma.sync.aligned.m16n8k16.row.col.f32.f16.f16.f32 " \
                 "{%0,%1,%2,%3}, {%4,%5,%6,%7}, {%8,%9}, {%0,%1,%2,%3};" \
                 : "+f"((d)[0]), "+f"((d)[1]), "+f"((d)[2]), "+f"((d)[3]) \
                 : "r"((a)[0]), "r"((a)[1]), "r"((a)[2]), "r"((a)[3]), \
                   "r"((b)[0]), "r"((b)[1]))

// ---------------------------------------------------------------------------
// fp32 -> fp16 convert (n multiple of 4)
// ---------------------------------------------------------------------------
__global__ void f2h_kernel(const float* __restrict__ in, __half* __restrict__ out, int n4)
{
    int i = blockIdx.x * 256 + threadIdx.x;
    if (i < n4) {
        float4 v = ((const float4*)in)[i];
        ((__half2*)out)[i * 2]     = __floats2half2_rn(v.x, v.y);
        ((__half2*)out)[i * 2 + 1] = __floats2half2_rn(v.z, v.w);
    }
}

// ---------------------------------------------------------------------------
// Transpose fp32 [R,C] -> fp16 [C,R]
// ---------------------------------------------------------------------------
__global__ __launch_bounds__(256)
void transpose_h_kernel(const float* __restrict__ in, __half* __restrict__ out,
                        int R, int C)
{
    __shared__ float t[32][33];
    int c0 = blockIdx.x * 32, r0 = blockIdx.y * 32;
    int x = threadIdx.x, y = threadIdx.y;
#pragma unroll
    for (int i = 0; i < 32; i += 8)
        t[y + i][x] = in[(size_t)(r0 + y + i) * C + c0 + x];
    __syncthreads();
#pragma unroll
    for (int i = 0; i < 32; i += 8)
        out[(size_t)(c0 + y + i) * R + r0 + x] = __float2half(t[x][y + i]);
}

// ---------------------------------------------------------------------------
// HMMA fp16 GEMM: C[M,N] = A[M,K] @ B[N,K]^T + bias[N]
// 128x128 tile, BK=32, 256 threads (8 warps, 2x4), warp tile 64x32.
// ---------------------------------------------------------------------------
#define SKEW 8
#define LDH (32 + SKEW)

__global__ __launch_bounds__(256)
void gemm_hmma_kernel(const __half* __restrict__ A, const __half* __restrict__ B,
                      const float* __restrict__ bias, float* __restrict__ C,
                      int M, int N, int K)
{
    __shared__ __half sA[128][LDH];
    __shared__ __half sB[128][LDH];

    const int tid = threadIdx.x;
    const int wid = tid >> 5, lane = tid & 31;
    const int wm = (wid >> 2) * 64;
    const int wn = (wid & 3) * 32;
    const int m0 = blockIdx.y * 128, n0 = blockIdx.x * 128;

    const int lr = tid >> 2;
    const int lc = (tid & 3) * 8;

    const __half* Ag = A + (size_t)m0 * K;
    const __half* Bg = B + (size_t)n0 * K;

    float acc[4][4][4];
#pragma unroll
    for (int i = 0; i < 4; i++)
#pragma unroll
        for (int j = 0; j < 4; j++)
#pragma unroll
            for (int r = 0; r < 4; r++) acc[i][j][r] = 0.f;

    const uint32_t sA_u = smem_u32(&sA[0][0]);
    const uint32_t sB_u = smem_u32(&sB[0][0]);

    const int a_row = wm + (lane & 15);
    const int a_col = (lane >> 4) * 8;
    const int b_row = wn + (lane & 7);
    const int b_col = ((lane >> 3) & 1) * 8;

    const int nstage = K >> 5;

    *(uint4*)&sA[lr][lc]      = *(const uint4*)(Ag + (size_t)lr * K + lc);
    *(uint4*)&sA[lr + 64][lc] = *(const uint4*)(Ag + (size_t)(lr + 64) * K + lc);
    *(uint4*)&sB[lr][lc]      = *(const uint4*)(Bg + (size_t)lr * K + lc);
    *(uint4*)&sB[lr + 64][lc] = *(const uint4*)(Bg + (size_t)(lr + 64) * K + lc);
    __syncthreads();

    uint4 pa0, pa1, pb0, pb1;
    for (int st = 0; st < nstage; st++) {
        const bool pf = (st + 1) < nstage;
        if (pf) {
            const int kn = (st + 1) << 5;
            pa0 = *(const uint4*)(Ag + (size_t)lr * K + kn + lc);
            pa1 = *(const uint4*)(Ag + (size_t)(lr + 64) * K + kn + lc);
            pb0 = *(const uint4*)(Bg + (size_t)lr * K + kn + lc);
            pb1 = *(const uint4*)(Bg + (size_t)(lr + 64) * K + kn + lc);
        }

#pragma unroll
        for (int ks = 0; ks < 2; ks++) {
            uint32_t af[4][4];
            uint32_t bf[4][2];
#pragma unroll
            for (int mt = 0; mt < 4; mt++) {
                uint32_t addr = sA_u +
                    (uint32_t)(((a_row + mt * 16) * LDH + ks * 16 + a_col) * 2);
                LDMATRIX_X4(af[mt][0], af[mt][1], af[mt][2], af[mt][3], addr);
            }
#pragma unroll
            for (int nt = 0; nt < 4; nt++) {
                uint32_t addr = sB_u +
                    (uint32_t)(((b_row + nt * 8) * LDH + ks * 16 + b_col) * 2);
                LDMATRIX_X2(bf[nt][0], bf[nt][1], addr);
            }
#pragma unroll
            for (int mt = 0; mt < 4; mt++)
#pragma unroll
                for (int nt = 0; nt < 4; nt++)
                    MMA16816(acc[mt][nt], af[mt], bf[nt]);
        }
        __syncthreads();
        if (pf) {
            *(uint4*)&sA[lr][lc] = pa0;
            *(uint4*)&sA[lr + 64][lc] = pa1;
            *(uint4*)&sB[lr][lc] = pb0;
            *(uint4*)&sB[lr + 64][lc] = pb1;
            __syncthreads();
        }
    }

    const int er = lane >> 2;
    const int ec = (lane & 3) * 2;
#pragma unroll
    for (int mt = 0; mt < 4; mt++) {
#pragma unroll
        for (int nt = 0; nt < 4; nt++) {
            int row = m0 + wm + mt * 16 + er;
            int col = n0 + wn + nt * 8 + ec;
            float2 bv = *(const float2*)&bias[col];
            float2 o;
            o.x = acc[mt][nt][0] + bv.x;
            o.y = acc[mt][nt][1] + bv.y;
            *(float2*)&C[(size_t)row * N + col] = o;
            o.x = acc[mt][nt][2] + bv.x;
            o.y = acc[mt][nt][3] + bv.y;
            *(float2*)&C[(size_t)(row + 8) * N + col] = o;
        }
    }
}

// ---------------------------------------------------------------------------
// RMS-norm + scale + RoPE + scatter (writes fp16 Q/K/V)
// ---------------------------------------------------------------------------
__global__ __launch_bounds__(256)
void normrope_kernel(const float* __restrict__ qs_in, const float* __restrict__ ks_in,
                     const float* __restrict__ qs_ctx, const float* __restrict__ ks_ctx)
{
    const int g = blockIdx.x;
    const int b = g / SEQ;
    const int nidx = g % SEQ;

    const float* src;
    const float* qs;
    const float* ks;
    if (nidx < SCTX) {
        src = g_qkv_ctx + ((size_t)b * SCTX + nidx) * (3 * DIM);
        qs = qs_ctx; ks = ks_ctx;
    } else {
        src = g_qkv_in + ((size_t)b * SIN + (nidx - SCTX)) * (3 * DIM);
        qs = qs_in; ks = ks_in;
    }

    __shared__ float sq[DIM];
    __shared__ float sk[DIM];
    __shared__ float red[20];

    const int tid = threadIdx.x;
    float aq = 0.f, ak = 0.f;
    for (int i = tid; i < DIM; i += 256) {
        float qv = src[i];
        float kv = src[DIM + i];
        sq[i] = qv; sk[i] = kv;
        aq += qv * qv; ak += kv * kv;
    }
#pragma unroll
    for (int o = 16; o > 0; o >>= 1) {
        aq += __shfl_xor_sync(0xffffffffu, aq, o);
        ak += __shfl_xor_sync(0xffffffffu, ak, o);
    }
    if ((tid & 31) == 0) { red[tid >> 5] = aq; red[8 + (tid >> 5)] = ak; }
    __syncthreads();
    if (tid == 0) {
        float s = 0.f;
        for (int w = 0; w < 8; w++) s += red[w];
        red[16] = rsqrtf(s / (float)DIM + 1e-6f);
        s = 0.f;
        for (int w = 0; w < 8; w++) s += red[8 + w];
        red[17] = rsqrtf(s / (float)DIM + 1e-6f);
    }
    __syncthreads();
    const float rq = red[16];
    const float rk = red[17];

    for (int p = tid; p < NH * 64; p += 256) {
        int h = p >> 6;
        int j = p & 63;
        int i1 = h * HD + j;
        int i2 = i1 + 64;
        float q1 = sq[i1] * rq * qs[i1];
        float q2 = sq[i2] * rq * qs[i2];
        float k1 = sk[i1] * rk * ks[i1];
        float k2 = sk[i2] * rk * ks[i2];
        float inv = powf(10000.f, -(float)j / 64.f);
        float ang = (float)nidx * inv;
        float c, s;
        sincosf(ang, &s, &c);
        size_t ob = ((size_t)(b * NH + h) * SEQ + nidx) * HD;
        g_q_h[ob + j]      = __float2half(q1 * c - q2 * s);
        g_q_h[ob + 64 + j] = __float2half(q2 * c + q1 * s);
        g_k_h[ob + j]      = __float2half(k1 * c - k2 * s);
        g_k_h[ob + 64 + j] = __float2half(k2 * c + k1 * s);
    }
    for (int i = tid; i < DIM; i += 256) {
        int h = i >> 7;
        int d = i & 127;
        g_v_h[((size_t)(b * NH + h) * SEQ + nidx) * HD + d] =
            __float2half(src[2 * DIM + i]);
    }
}

// ---------------------------------------------------------------------------
// Flash attention, HMMA fp16. BQ=128, BK=64, D=128, 256 threads (8 warps).
// Warp w owns q-rows wm=w*16..+15. fp16 Q/K/V inputs, fp32 softmax/accum.
// Output fp16 to g_attn_h[b][n][h*128+d].
// ---------------------------------------------------------------------------
#define APAD 136   // 128 + 8 halves per row

__global__ __launch_bounds__(256)
void attn_hmma_kernel()
{
    extern __shared__ __half smh[];
    __half* Qs = smh;                   // 128 x APAD
    __half* Ks = Qs + 128 * APAD;       // 64 x APAD
    __half* Vs = Ks + 64 * APAD;        // 64 x APAD

    const int bh = blockIdx.x;
    const int q0 = blockIdx.y * 128;
    const int b = bh / NH;
    const int h = bh % NH;
    const __half* Qb = g_q_h + (size_t)bh * SEQ * HD;
    const __half* Kb = g_k_h + (size_t)bh * SEQ * HD;
    const __half* Vb = g_v_h + (size_t)bh * SEQ * HD;

    const int tid = threadIdx.x;
    const int wid = tid >> 5, lane = tid & 31;
    const int wm = wid * 16;
    const int r  = lane >> 2;
    const int qc = (lane & 3) * 2;

    const uint32_t Qs_u = smem_u32(Qs);
    const uint32_t Ks_u = smem_u32(Ks);
    const uint32_t Vs_u = smem_u32(Vs);

    // Load Q tile (fp16, uint4 = 8 halves)
    for (int i = tid; i < 128 * 16; i += 256) {
        int row = i >> 4, c8 = i & 15;
        *(uint4*)(Qs + row * APAD + c8 * 8) =
            *(const uint4*)(Qb + (size_t)(q0 + row) * HD + c8 * 8);
    }

    float oacc[16][4];
#pragma unroll
    for (int dt = 0; dt < 16; dt++)
#pragma unroll
        for (int j = 0; j < 4; j++) oacc[dt][j] = 0.f;
    float mrow0 = -1e30f, mrow1 = -1e30f;
    float lrow0 = 0.f,    lrow1 = 0.f;

    const float scale = 0.08838834764831845f;   // 1/sqrt(128)

    for (int k0 = 0; k0 < SEQ; k0 += 64) {
        // Load K, V tiles (fp16)
        for (int i = tid; i < 64 * 16; i += 256) {
            int row = i >> 4, c8 = i & 15;
            *(uint4*)(Ks + row * APAD + c8 * 8) =
                *(const uint4*)(Kb + (size_t)(k0 + row) * HD + c8 * 8);
            *(uint4*)(Vs + row * APAD + c8 * 8) =
                *(const uint4*)(Vb + (size_t)(k0 + row) * HD + c8 * 8);
        }
        __syncthreads();

        // Scores S[16][64] = Q_tile . K_tile^T
        float sacc[8][4];
#pragma unroll
        for (int nt = 0; nt < 8; nt++)
#pragma unroll
            for (int j = 0; j < 4; j++) sacc[nt][j] = 0.f;

#pragma unroll
        for (int kd = 0; kd < 8; kd++) {
            uint32_t af[4];
            uint32_t a_addr = Qs_u +
                (uint32_t)(((wm + (lane & 15)) * APAD + kd * 16 + (lane >> 4) * 8) * 2);
            LDMATRIX_X4(af[0], af[1], af[2], af[3], a_addr);
#pragma unroll
            for (int nt = 0; nt < 8; nt++) {
                uint32_t bf[2];
                uint32_t b_addr = Ks_u +
                    (uint32_t)(((nt * 8 + (lane & 7)) * APAD + kd * 16 + ((lane >> 3) & 1) * 8) * 2);
                LDMATRIX_X2(bf[0], bf[1], b_addr);
                MMA16816(sacc[nt], af, bf);
            }
        }

        // Online softmax on fragments.
        float mx0 = -1e30f, mx1 = -1e30f;
#pragma unroll
        for (int nt = 0; nt < 8; nt++) {
            sacc[nt][0] *= scale; sacc[nt][1] *= scale;
            sacc[nt][2] *= scale; sacc[nt][3] *= scale;
            mx0 = fmaxf(mx0, fmaxf(sacc[nt][0], sacc[nt][1]));
            mx1 = fmaxf(mx1, fmaxf(sacc[nt][2], sacc[nt][3]));
        }
        mx0 = fmaxf(mx0, __shfl_xor_sync(0xffffffffu, mx0, 1));
        mx0 = fmaxf(mx0, __shfl_xor_sync(0xffffffffu, mx0, 2));
        mx1 = fmaxf(mx1, __shfl_xor_sync(0xffffffffu, mx1, 1));
        mx1 = fmaxf(mx1, __shfl_xor_sync(0xffffffffu, mx1, 2));

        float mn0 = fmaxf(mrow0, mx0);
        float mn1 = fmaxf(mrow1, mx1);
        float corr0 = __expf(mrow0 - mn0);
        float corr1 = __expf(mrow1 - mn1);

        float s0 = 0.f, s1 = 0.f;
#pragma unroll
        for (int nt = 0; nt < 8; nt++) {
            sacc[nt][0] = __expf(sacc[nt][0] - mn0);
            sacc[nt][1] = __expf(sacc[nt][1] - mn0);
            sacc[nt][2] = __expf(sacc[nt][2] - mn1);
            sacc[nt][3] = __expf(sacc[nt][3] - mn1);
            s0 += sacc[nt][0] + sacc[nt][1];
            s1 += sacc[nt][2] + sacc[nt][3];
        }
        s0 += __shfl_xor_sync(0xffffffffu, s0, 1);
        s0 += __shfl_xor_sync(0xffffffffu, s0, 2);
        s1 += __shfl_xor_sync(0xffffffffu, s1, 1);
        s1 += __shfl_xor_sync(0xffffffffu, s1, 2);

        lrow0 = lrow0 * corr0 + s0;  mrow0 = mn0;
        lrow1 = lrow1 * corr1 + s1;  mrow1 = mn1;

#pragma unroll
        for (int dt = 0; dt < 16; dt++) {
            oacc[dt][0] *= corr0; oacc[dt][1] *= corr0;
            oacc[dt][2] *= corr1; oacc[dt][3] *= corr1;
        }

        // P -> fp16 A-fragments
        uint32_t pf[4][4];
#pragma unroll
        for (int kt = 0; kt < 4; kt++) {
            __half2 h0 = __floats2half2_rn(sacc[2 * kt][0],     sacc[2 * kt][1]);
            __half2 h1 = __floats2half2_rn(sacc[2 * kt][2],     sacc[2 * kt][3]);
            __half2 h2 = __floats2half2_rn(sacc[2 * kt + 1][0], sacc[2 * kt + 1][1]);
            __half2 h3 = __floats2half2_rn(sacc[2 * kt + 1][2], sacc[2 * kt + 1][3]);
            pf[kt][0] = *(uint32_t*)&h0;
            pf[kt][1] = *(uint32_t*)&h1;
            pf[kt][2] = *(uint32_t*)&h2;
            pf[kt][3] = *(uint32_t*)&h3;
        }

        // O += P . V  (V via trans ldmatrix from [s][d] storage)
        const int v_row = (lane & 7) + 8 * ((lane >> 3) & 1);
#pragma unroll
        for (int dt = 0; dt < 16; dt++) {
#pragma unroll
            for (int kt = 0; kt < 4; kt++) {
                uint32_t vf[2];
                uint32_t v_addr = Vs_u +
                    (uint32_t)(((kt * 16 + v_row) * APAD + dt * 8) * 2);
                LDMATRIX_X2T(vf[0], vf[1], v_addr);
                MMA16816(oacc[dt], pf[kt], vf);
            }
        }
        __syncthreads();
    }

    // Epilogue -> g_attn_h[b][q][h*128+d], fp16
    float inv0 = 1.f / lrow0;
    float inv1 = 1.f / lrow1;
    int qrow0 = q0 + wm + r;
    int qrow1 = qrow0 + 8;
    __half* o0 = g_attn_h + ((size_t)b * SEQ + qrow0) * DIM + h * HD;
    __half* o1 = g_attn_h + ((size_t)b * SEQ + qrow1) * DIM + h * HD;
#pragma unroll
    for (int dt = 0; dt < 16; dt++) {
        __half2 w0 = __floats2half2_rn(oacc[dt][0] * inv0, oacc[dt][1] * inv0);
        __half2 w1 = __floats2half2_rn(oacc[dt][2] * inv1, oacc[dt][3] * inv1);
        *(__half2*)(o0 + dt * 8 + qc) = w0;
        *(__half2*)(o1 + dt * 8 + qc) = w1;
    }
}

// ---------------------------------------------------------------------------
// Launch
// ---------------------------------------------------------------------------
extern "C" void kernel_launch(void* const* d_in, const int* in_sizes, int n_in,
                              void* d_out, int out_size)
{
    const float* input     = (const float*)d_in[0];
    const float* context   = (const float*)d_in[1];
    const float* W_qkv_in  = (const float*)d_in[2];
    const float* b_qkv_in  = (const float*)d_in[3];
    const float* W_qkv_ctx = (const float*)d_in[4];
    const float* b_qkv_ctx = (const float*)d_in[5];
    const float* qs_in     = (const float*)d_in[6];
    const float* ks_in     = (const float*)d_in[7];
    const float* qs_ctx    = (const float*)d_in[8];
    const float* ks_ctx    = (const float*)d_in[9];
    const float* W_out_in  = (const float*)d_in[10];
    const float* b_out_in  = (const float*)d_in[11];
    const float* W_out_ctx = (const float*)d_in[12];
    const float* b_out_ctx = (const float*)d_in[13];
    float* out = (float*)d_out;

    float *p_qkv_in, *p_qkv_ctx;
    __half *p_in_h, *p_ctx_h, *p_attn_h;
    __half *p_wqi, *p_wqc, *p_woi, *p_woc;
    cudaGetSymbolAddress((void**)&p_qkv_in, g_qkv_in);
    cudaGetSymbolAddress((void**)&p_qkv_ctx, g_qkv_ctx);
    cudaGetSymbolAddress((void**)&p_in_h, g_in_h);
    cudaGetSymbolAddress((void**)&p_ctx_h, g_ctx_h);
    cudaGetSymbolAddress((void**)&p_attn_h, g_attn_h);
    cudaGetSymbolAddress((void**)&p_wqi, g_wqkv_in_h);
    cudaGetSymbolAddress((void**)&p_wqc, g_wqkv_ctx_h);
    cudaGetSymbolAddress((void**)&p_woi, g_wout_in_h);
    cudaGetSymbolAddress((void**)&p_woc, g_wout_ctx_h);

    // 0) Convert activations + transpose weights to fp16 K-major
    {
        int n4 = (BATCH * SIN * DIM) / 4;
        f2h_kernel<<<(n4 + 255) / 256, 256>>>(input, p_in_h, n4);
        n4 = (BATCH * SCTX * DIM) / 4;
        f2h_kernel<<<(n4 + 255) / 256, 256>>>(context, p_ctx_h, n4);
    }
    {
        dim3 blk(32, 8);
        dim3 g1(3 * DIM / 32, DIM / 32);
        transpose_h_kernel<<<g1, blk>>>(W_qkv_in, p_wqi, DIM, 3 * DIM);
        transpose_h_kernel<<<g1, blk>>>(W_qkv_ctx, p_wqc, DIM, 3 * DIM);
        dim3 g2(DIM / 32, DIM / 32);
        transpose_h_kernel<<<g2, blk>>>(W_out_in, p_woi, DIM, DIM);
        transpose_h_kernel<<<g2, blk>>>(W_out_ctx, p_woc, DIM, DIM);
    }

    // 1) QKV projections (HMMA fp16)
    {
        dim3 grid(3 * DIM / 128, (BATCH * SIN) / 128);     // 36 x 32
        gemm_hmma_kernel<<<grid, 256>>>(p_in_h, p_wqi, b_qkv_in, p_qkv_in,
                                        BATCH * SIN, 3 * DIM, DIM);
    }
    {
        dim3 grid(3 * DIM / 128, (BATCH * SCTX) / 128);    // 36 x 4
        gemm_hmma_kernel<<<grid, 256>>>(p_ctx_h, p_wqc, b_qkv_ctx, p_qkv_ctx,
                                        BATCH * SCTX, 3 * DIM, DIM);
    }

    // 2) RMS norm + RoPE + scatter (fp16 Q/K/V out)
    normrope_kernel<<<BATCH * SEQ, 256>>>(qs_in, ks_in, qs_ctx, ks_ctx);

    // 3) Attention (HMMA fp16, BQ=128) -> writes g_attn_h
    {
        size_t smem = (size_t)(128 + 64 + 64) * APAD * sizeof(__half);  // 69632 B
        cudaFuncSetAttribute(attn_hmma_kernel,
                             cudaFuncAttributeMaxDynamicSharedMemorySize,
                             (int)smem);
        dim3 grid(BATCH * NH, SEQ / 128);                  // 24 x 18
        attn_hmma_kernel<<<grid, 256, smem>>>();
    }

    // 4) Output projections (HMMA fp16)
    for (int b = 0; b < BATCH; b++) {
        dim3 grid(DIM / 128, SIN / 128);                   // 12 x 16
        gemm_hmma_kernel<<<grid, 256>>>(
            p_attn_h + ((size_t)b * SEQ + SCTX) * DIM,
            p_woi, b_out_in,
            out + (size_t)b * SIN * DIM,
            SIN, DIM, DIM);
    }
    for (int b = 0; b < BATCH; b++) {
        dim3 grid(DIM / 128, SCTX / 128);                  // 12 x 2
        gemm_hmma_kernel<<<grid, 256>>>(
            p_attn_h + (size_t)b * SEQ * DIM,
            p_woc, b_out_ctx,
            out + (size_t)BATCH * SIN * DIM + (size_t)b * SCTX * DIM,
            SCTX, DIM, DIM);
    }
}